// round 11
// baseline (speedup 1.0000x reference)
#include <cuda_runtime.h>
#include <cstdint>

#define N_STEPS 1000
#define ELEMS 6

// Per-step key schedule, 2 uint4 records:
//  A = {k0, k1, k2, k2+1},  B = {k0+2, k1+3, k2+4, k0+5}
__device__ uint4 g_keysA[N_STEPS + 1];
__device__ uint4 g_keysB[N_STEPS + 1];

// pre-scale all erfinv coefficients by 0.1 * sqrt(2)
#define SC(c) (0.14142136f * (c))

// guaranteed single-instruction FFMA with [0,1] saturation (the clip)
__device__ __forceinline__ float fma_sat(float a, float b, float c) {
    float d;
    asm("fma.rn.sat.f32 %0, %1, %2, %3;" : "=f"(d) : "f"(a), "f"(b), "f"(c));
    return d;
}

// forced IMAD add (fma pipe): d = a*one + b, `one` is an opaque runtime 1
__device__ __forceinline__ uint32_t addm(uint32_t a, uint32_t b, uint32_t one) {
    uint32_t d;
    asm("mad.lo.u32 %0, %1, %2, %3;" : "=r"(d) : "r"(a), "r"(one), "r"(b));
    return d;
}

// ---------------- Threefry-2x32 ----------------
// round with the add forced onto the IMAD pipe; SHF+LOP3 stay on alu
__device__ __forceinline__ void rsm(uint32_t& x0, uint32_t& x1, int r, uint32_t one) {
    x0 = addm(x1, x0, one);                   // IMAD
    x1 = __funnelshift_l(x1, x1, r) ^ x0;     // SHF + LOP3 (alu)
}

// full 20-round block (c0 = 0 folded), returns o0 ^ o1 (partitionable random_bits).
// 4 key-injection points: x0-injection merged into the round add as one IADD3
// (x0 + k + x1), saving 4 ops vs the separate-injection form.
__device__ __forceinline__ uint32_t tf_xor(uint4 ka, uint4 kb, uint32_t c1, uint32_t one) {
    uint32_t x1 = c1 + ka.y;                  // alu add
    uint32_t x0 = addm(x1, ka.x, one);        // round-1 add, x0-init folded (IMAD)
    x1 = __funnelshift_l(x1, x1, 13) ^ x0;
    rsm(x0, x1, 15, one); rsm(x0, x1, 26, one); rsm(x0, x1, 6, one);
    x1 += ka.w;                               // x1 += k2+1
    x0 = x0 + ka.y + x1;                      // IADD3: (x0 + k1) + x1  [round 5 add]
    x1 = __funnelshift_l(x1, x1, 17) ^ x0;
    rsm(x0, x1, 29, one); rsm(x0, x1, 16, one); rsm(x0, x1, 24, one);
    x1 += kb.x;                               // x1 += k0+2
    x0 = x0 + ka.z + x1;                      // IADD3: (x0 + k2) + x1  [round 9 add]
    x1 = __funnelshift_l(x1, x1, 13) ^ x0;
    rsm(x0, x1, 15, one); rsm(x0, x1, 26, one); rsm(x0, x1, 6, one);
    x1 += kb.y;                               // x1 += k1+3
    x0 = x0 + ka.x + x1;                      // IADD3: (x0 + k0) + x1  [round 13 add]
    x1 = __funnelshift_l(x1, x1, 17) ^ x0;
    rsm(x0, x1, 29, one); rsm(x0, x1, 16, one); rsm(x0, x1, 24, one);
    x1 += kb.z;                               // x1 += k2+4
    x0 = x0 + ka.y + x1;                      // IADD3: (x0 + k1) + x1  [round 17 add]
    x1 = __funnelshift_l(x1, x1, 13) ^ x0;
    rsm(x0, x1, 15, one); rsm(x0, x1, 26, one); rsm(x0, x1, 6, one);
    return (x0 + ka.z) ^ (x1 + kb.w);         // (x0+k2) ^ (x1+k0+5)
}

// plain scalar threefry for key prep (perf-irrelevant)
__device__ __forceinline__ void rs_s(uint32_t& x0, uint32_t& x1, int r) {
    x0 += x1; x1 = __funnelshift_l(x1, x1, r) ^ x0;
}
__device__ void threefry2x32_full(uint32_t k0, uint32_t k1, uint32_t c0, uint32_t c1,
                                  uint32_t& o0, uint32_t& o1) {
    const uint32_t k2 = k0 ^ k1 ^ 0x1BD11BDAu;
    uint32_t x0 = c0 + k0, x1 = c1 + k1;
    rs_s(x0,x1,13); rs_s(x0,x1,15); rs_s(x0,x1,26); rs_s(x0,x1,6);
    x0 += k1; x1 += k2 + 1u;
    rs_s(x0,x1,17); rs_s(x0,x1,29); rs_s(x0,x1,16); rs_s(x0,x1,24);
    x0 += k2; x1 += k0 + 2u;
    rs_s(x0,x1,13); rs_s(x0,x1,15); rs_s(x0,x1,26); rs_s(x0,x1,6);
    x0 += k0; x1 += k1 + 3u;
    rs_s(x0,x1,17); rs_s(x0,x1,29); rs_s(x0,x1,16); rs_s(x0,x1,24);
    x0 += k1; x1 += k2 + 4u;
    rs_s(x0,x1,13); rs_s(x0,x1,15); rs_s(x0,x1,26); rs_s(x0,x1,6);
    o0 = x0 + k2; o1 = x1 + k0 + 5u;
}

__global__ void prep_keys_kernel() {
    int t = threadIdx.x;
    if (t > N_STEPS) return;
    uint32_t kk1 = (t < N_STEPS) ? 1u : 2u;
    uint32_t cc1 = (t < N_STEPS) ? (uint32_t)t : 999u;
    uint32_t o0, o1;
    threefry2x32_full(0u, kk1, 0u, cc1, o0, o1);
    uint32_t k0 = o0, k1 = o1, k2 = o0 ^ o1 ^ 0x1BD11BDAu;
    g_keysA[t] = make_uint4(k0, k1, k2, k2 + 1u);
    g_keysB[t] = make_uint4(k0 + 2u, k1 + 3u, k2 + 4u, k0 + 5u);
}

// rare tail branch of erfinv (w >= 5), coefficients pre-scaled; z = w - 2.5
__device__ __noinline__ float tailp(float z) {
    float zz = __fsqrt_rn(z + 2.5f) - 3.0f;
    float p = SC(-0.000200214257f);
    p = fmaf(p, zz, SC(0.000100950558f));
    p = fmaf(p, zz, SC(0.00134934322f));
    p = fmaf(p, zz, SC(-0.00367342844f));
    p = fmaf(p, zz, SC(0.00573950773f));
    p = fmaf(p, zz, SC(-0.0076224613f));
    p = fmaf(p, zz, SC(0.00943887047f));
    p = fmaf(p, zz, SC(1.00167406f));
    p = fmaf(p, zz, SC(2.83297682f));
    return p;
}

// central pipeline: bits -> {xx, z, p_central}   (no branch; tail patched by caller)
__device__ __forceinline__ void noise_central(uint32_t b, uint32_t mhi9,
                                              float& xx, float& z, float& p) {
    uint32_t fbits;   // (b >> 9) | 0x3f800000  ==  hi(b * 2^23) + 0x3f800000, one IMAD.HI
    asm("mad.hi.u32 %0, %1, %2, %3;"
        : "=r"(fbits) : "r"(b), "r"(mhi9), "r"(0x3f800000u));
    float f = __uint_as_float(fbits);                // [1, 2)
    float u = f - 1.0f;                              // [0, 1), exact
    // two-op form REQUIRED: -2.99999994f is not representable (rounds to -3.0f),
    // which would make xx hit exactly -1.0 for bits < 512 -> log(0) -> NaN.
    xx = fmaf(u, 2.0f, -0.99999994f);                // uniform in [nextafter(-1,0), 1)
    float t = fmaf(xx, -xx, 1.0f);                   // 1 - x^2 > 0
    z = fmaf(__log2f(t), -0.69314718f, -2.5f);       // w - 2.5
    // central Giles poly, z^8 and z^7 terms dropped: per-step noise error is
    // odd-symmetric in xx (zero-mean across draws); predicted final rel_err <= ~1e-4
    p = SC(-3.5233877e-06f);
    p = fmaf(p, z, SC(-4.39150654e-06f));
    p = fmaf(p, z, SC(0.00021858087f));
    p = fmaf(p, z, SC(-0.00125372503f));
    p = fmaf(p, z, SC(-0.00417768164f));
    p = fmaf(p, z, SC(0.246640727f));
    p = fmaf(p, z, SC(1.50140941f));
}

// 768 threads/SM (3 blocks) -> 85-reg budget: room for 6 fully-parallel chains
__global__ void __launch_bounds__(256, 3)
diffusion_kernel(const float* __restrict__ x, float* __restrict__ out, int n,
                 uint32_t mhi9, uint32_t one) {
    __shared__ uint4 sA[N_STEPS + 1];
    __shared__ uint4 sB[N_STEPS + 1];
    for (int i = threadIdx.x; i <= N_STEPS; i += 256) {
        sA[i] = g_keysA[i];
        sB[i] = g_keysB[i];
    }
    __syncthreads();

    unsigned tid  = blockIdx.x * 256u + threadIdx.x;
    unsigned base = tid * (unsigned)ELEMS;
    if (base >= (unsigned)n) return;

    if (base + (unsigned)ELEMS <= (unsigned)n) {
        // ---- main path: 6 independent scalar chains per thread (ILP-6) ----
        float v[ELEMS];
        {   // 6 floats = 3x float2 (8-byte aligned)
            const float2* xp = reinterpret_cast<const float2*>(x + base);
            float2 a = xp[0], b = xp[1], c = xp[2];
            v[0] = a.x; v[1] = a.y; v[2] = b.x; v[3] = b.y; v[4] = c.x; v[5] = c.y;
        }
        uint32_t cc[ELEMS];
        #pragma unroll
        for (int j = 0; j < ELEMS; ++j) cc[j] = base + (uint32_t)j;
        const unsigned wmask = __activemask();

        #pragma unroll 1
        for (int t = 0; t < N_STEPS; ++t) {
            uint4 ka = sA[t];
            uint4 kb = sB[t];
            uint32_t b[ELEMS];
            #pragma unroll
            for (int j = 0; j < ELEMS; ++j)
                b[j] = tf_xor(ka, kb, cc[j], one);
            float xx[ELEMS], z[ELEMS], p[ELEMS];
            #pragma unroll
            for (int j = 0; j < ELEMS; ++j)
                noise_central(b[j], mhi9, xx[j], z[j], p[j]);
            // warp-uniform rare guard: no divergence on the common path
            float zm = fmaxf(fmaxf(fmaxf(z[0], z[1]), fmaxf(z[2], z[3])),
                             fmaxf(z[4], z[5]));
            if (__builtin_expect(__any_sync(wmask, zm >= 2.5f), 0)) {
                #pragma unroll
                for (int j = 0; j < ELEMS; ++j)
                    if (z[j] >= 2.5f) p[j] = tailp(z[j]);
            }
            #pragma unroll
            for (int j = 0; j < ELEMS; ++j)
                v[j] = fma_sat(p[j], xx[j], v[j]);   // clip(v + noise)
        }
        {   // reverse diffusion: single denoise step (subtract)
            uint4 ka = sA[N_STEPS];
            uint4 kb = sB[N_STEPS];
            #pragma unroll
            for (int j = 0; j < ELEMS; ++j) {
                uint32_t b = tf_xor(ka, kb, cc[j], one);
                float xx, z, p;
                noise_central(b, mhi9, xx, z, p);
                if (z >= 2.5f) p = tailp(z);
                v[j] = fma_sat(-p, xx, v[j]);
            }
        }
        {
            float2* op = reinterpret_cast<float2*>(out + base);
            op[0] = make_float2(v[0], v[1]);
            op[1] = make_float2(v[2], v[3]);
            op[2] = make_float2(v[4], v[5]);
        }
    } else {
        // scalar tail path (not hit when n % 6 == 0, e.g. the 25165824-element shape)
        for (unsigned e = base; e < (unsigned)n; ++e) {
            float vv = x[e];
            for (int t = 0; t < N_STEPS; ++t) {
                float xx, z, p;
                noise_central(tf_xor(sA[t], sB[t], e, one), mhi9, xx, z, p);
                if (z >= 2.5f) p = tailp(z);
                vv = fma_sat(p, xx, vv);
            }
            float xx, z, p;
            noise_central(tf_xor(sA[N_STEPS], sB[N_STEPS], e, one), mhi9, xx, z, p);
            if (z >= 2.5f) p = tailp(z);
            out[e] = fma_sat(-p, xx, vv);
        }
    }
}

extern "C" void kernel_launch(void* const* d_in, const int* in_sizes, int n_in,
                              void* d_out, int out_size) {
    const float* x = (const float*)d_in[0];
    float* out     = (float*)d_out;
    int n = out_size;

    prep_keys_kernel<<<1, 1024>>>();

    unsigned threads = (unsigned)((n + ELEMS - 1) / ELEMS);
    unsigned blocks  = (threads + 255u) / 256u;
    // mhi9 = 1<<23 (for IMAD.HI) and one = 1 (for IMAD adds) kept opaque to ptxas
    diffusion_kernel<<<blocks, 256>>>(x, out, n, 1u << 23, 1u);
}

// round 12
// speedup vs baseline: 1.0393x; 1.0393x over previous
#include <cuda_runtime.h>
#include <cstdint>

#define N_STEPS 1000
#define ELEMS 6

// Per-step key schedule, 2 uint4 records:
//  A = {k0, k1, k2, k2+1},  B = {k0+2, k1+3, k2+4, k0+5}
__device__ uint4 g_keysA[N_STEPS + 1];
__device__ uint4 g_keysB[N_STEPS + 1];

// pre-scale all erfinv coefficients by 0.1 * sqrt(2)
#define SC(c) (0.14142136f * (c))

// guaranteed single-instruction FFMA with [0,1] saturation (the clip)
__device__ __forceinline__ float fma_sat(float a, float b, float c) {
    float d;
    asm("fma.rn.sat.f32 %0, %1, %2, %3;" : "=f"(d) : "f"(a), "f"(b), "f"(c));
    return d;
}

// forced IMAD add (fma pipe): d = a*one + b, `one` is an opaque runtime 1
__device__ __forceinline__ uint32_t addm(uint32_t a, uint32_t b, uint32_t one) {
    uint32_t d;
    asm("mad.lo.u32 %0, %1, %2, %3;" : "=r"(d) : "r"(a), "r"(one), "r"(b));
    return d;
}

// ---------------- Threefry-2x32 ----------------
// round with the add forced onto the IMAD pipe; SHF+LOP3 stay on alu
__device__ __forceinline__ void rsm(uint32_t& x0, uint32_t& x1, int r, uint32_t one) {
    x0 = addm(x1, x0, one);                   // IMAD
    x1 = __funnelshift_l(x1, x1, r) ^ x0;     // SHF + LOP3 (alu)
}

// full 20-round block (c0 = 0 folded), returns o0 ^ o1 (partitionable random_bits)
// R10 form: separate key injections on the IMAD pipe (the R11 IADD3 merge put
// them back on alu and regressed — do not merge).
__device__ __forceinline__ uint32_t tf_xor(uint4 ka, uint4 kb, uint32_t c1, uint32_t one) {
    uint32_t x1 = c1 + ka.y;                  // alu add
    uint32_t x0 = addm(x1, ka.x, one);        // round-1 add, x0-init folded (IMAD)
    x1 = __funnelshift_l(x1, x1, 13) ^ x0;
    rsm(x0, x1, 15, one); rsm(x0, x1, 26, one); rsm(x0, x1, 6, one);
    x0 = addm(x0, ka.y, one); x1 += ka.w;     // += k1 (IMAD) | += k2+1
    rsm(x0, x1, 17, one); rsm(x0, x1, 29, one); rsm(x0, x1, 16, one); rsm(x0, x1, 24, one);
    x0 = addm(x0, ka.z, one); x1 += kb.x;     // += k2 | += k0+2
    rsm(x0, x1, 13, one); rsm(x0, x1, 15, one); rsm(x0, x1, 26, one); rsm(x0, x1, 6, one);
    x0 = addm(x0, ka.x, one); x1 += kb.y;     // += k0 | += k1+3
    rsm(x0, x1, 17, one); rsm(x0, x1, 29, one); rsm(x0, x1, 16, one); rsm(x0, x1, 24, one);
    x0 = addm(x0, ka.y, one); x1 += kb.z;     // += k1 | += k2+4
    rsm(x0, x1, 13, one); rsm(x0, x1, 15, one); rsm(x0, x1, 26, one); rsm(x0, x1, 6, one);
    return addm(x0, ka.z, one) ^ addm(x1, kb.w, one);   // (x0+k2) ^ (x1+k0+5)
}

// plain scalar threefry for key prep (perf-irrelevant)
__device__ __forceinline__ void rs_s(uint32_t& x0, uint32_t& x1, int r) {
    x0 += x1; x1 = __funnelshift_l(x1, x1, r) ^ x0;
}
__device__ void threefry2x32_full(uint32_t k0, uint32_t k1, uint32_t c0, uint32_t c1,
                                  uint32_t& o0, uint32_t& o1) {
    const uint32_t k2 = k0 ^ k1 ^ 0x1BD11BDAu;
    uint32_t x0 = c0 + k0, x1 = c1 + k1;
    rs_s(x0,x1,13); rs_s(x0,x1,15); rs_s(x0,x1,26); rs_s(x0,x1,6);
    x0 += k1; x1 += k2 + 1u;
    rs_s(x0,x1,17); rs_s(x0,x1,29); rs_s(x0,x1,16); rs_s(x0,x1,24);
    x0 += k2; x1 += k0 + 2u;
    rs_s(x0,x1,13); rs_s(x0,x1,15); rs_s(x0,x1,26); rs_s(x0,x1,6);
    x0 += k0; x1 += k1 + 3u;
    rs_s(x0,x1,17); rs_s(x0,x1,29); rs_s(x0,x1,16); rs_s(x0,x1,24);
    x0 += k1; x1 += k2 + 4u;
    rs_s(x0,x1,13); rs_s(x0,x1,15); rs_s(x0,x1,26); rs_s(x0,x1,6);
    o0 = x0 + k2; o1 = x1 + k0 + 5u;
}

__global__ void prep_keys_kernel() {
    int t = threadIdx.x;
    if (t > N_STEPS) return;
    uint32_t kk1 = (t < N_STEPS) ? 1u : 2u;
    uint32_t cc1 = (t < N_STEPS) ? (uint32_t)t : 999u;
    uint32_t o0, o1;
    threefry2x32_full(0u, kk1, 0u, cc1, o0, o1);
    uint32_t k0 = o0, k1 = o1, k2 = o0 ^ o1 ^ 0x1BD11BDAu;
    g_keysA[t] = make_uint4(k0, k1, k2, k2 + 1u);
    g_keysB[t] = make_uint4(k0 + 2u, k1 + 3u, k2 + 4u, k0 + 5u);
}

// rare tail branch of erfinv (w >= 5), coefficients pre-scaled; z = w - 2.5
__device__ __noinline__ float tailp(float z) {
    float zz = __fsqrt_rn(z + 2.5f) - 3.0f;
    float p = SC(-0.000200214257f);
    p = fmaf(p, zz, SC(0.000100950558f));
    p = fmaf(p, zz, SC(0.00134934322f));
    p = fmaf(p, zz, SC(-0.00367342844f));
    p = fmaf(p, zz, SC(0.00573950773f));
    p = fmaf(p, zz, SC(-0.0076224613f));
    p = fmaf(p, zz, SC(0.00943887047f));
    p = fmaf(p, zz, SC(1.00167406f));
    p = fmaf(p, zz, SC(2.83297682f));
    return p;
}

// central pipeline: bits -> {xx, z, p_central}   (no branch; tail patched by caller)
__device__ __forceinline__ void noise_central(uint32_t b, uint32_t mhi9,
                                              float& xx, float& z, float& p) {
    uint32_t fbits;   // (b >> 9) | 0x3f800000  ==  hi(b * 2^23) + 0x3f800000, one IMAD.HI
    asm("mad.hi.u32 %0, %1, %2, %3;"
        : "=r"(fbits) : "r"(b), "r"(mhi9), "r"(0x3f800000u));
    float f = __uint_as_float(fbits);                // [1, 2)
    float u = f - 1.0f;                              // [0, 1), exact
    // two-op form REQUIRED: -2.99999994f is not representable (rounds to -3.0f),
    // which would make xx hit exactly -1.0 for bits < 512 -> log(0) -> NaN.
    xx = fmaf(u, 2.0f, -0.99999994f);                // uniform in [nextafter(-1,0), 1)
    float t = fmaf(xx, -xx, 1.0f);                   // 1 - x^2 > 0
    z = fmaf(__log2f(t), -0.69314718f, -2.5f);       // w - 2.5
    // central Giles poly, z^8/z^7/z^6 terms dropped. Dropped-term error is odd in
    // xx -> zero-mean per step. Measured ladder: z^8 drop -> 6.6e-6, +z^7 -> 2.9e-5;
    // +z^6 predicted ~1.4e-4 final (7x under the 1e-3 threshold).
    p = SC(-4.39150654e-06f);
    p = fmaf(p, z, SC(0.00021858087f));
    p = fmaf(p, z, SC(-0.00125372503f));
    p = fmaf(p, z, SC(-0.00417768164f));
    p = fmaf(p, z, SC(0.246640727f));
    p = fmaf(p, z, SC(1.50140941f));
}

// 768 threads/SM (3 blocks) -> 85-reg budget: room for 6 fully-parallel chains
__global__ void __launch_bounds__(256, 3)
diffusion_kernel(const float* __restrict__ x, float* __restrict__ out, int n,
                 uint32_t mhi9, uint32_t one) {
    __shared__ uint4 sA[N_STEPS + 1];
    __shared__ uint4 sB[N_STEPS + 1];
    for (int i = threadIdx.x; i <= N_STEPS; i += 256) {
        sA[i] = g_keysA[i];
        sB[i] = g_keysB[i];
    }
    __syncthreads();

    unsigned tid  = blockIdx.x * 256u + threadIdx.x;
    unsigned base = tid * (unsigned)ELEMS;
    if (base >= (unsigned)n) return;

    if (base + (unsigned)ELEMS <= (unsigned)n) {
        // ---- main path: 6 independent scalar chains per thread (ILP-6) ----
        float v[ELEMS];
        {   // 6 floats = 3x float2 (8-byte aligned)
            const float2* xp = reinterpret_cast<const float2*>(x + base);
            float2 a = xp[0], b = xp[1], c = xp[2];
            v[0] = a.x; v[1] = a.y; v[2] = b.x; v[3] = b.y; v[4] = c.x; v[5] = c.y;
        }
        uint32_t cc[ELEMS];
        #pragma unroll
        for (int j = 0; j < ELEMS; ++j) cc[j] = base + (uint32_t)j;
        const unsigned wmask = __activemask();

        #pragma unroll 1
        for (int t = 0; t < N_STEPS; ++t) {
            uint4 ka = sA[t];
            uint4 kb = sB[t];
            uint32_t b[ELEMS];
            #pragma unroll
            for (int j = 0; j < ELEMS; ++j)
                b[j] = tf_xor(ka, kb, cc[j], one);
            float xx[ELEMS], z[ELEMS], p[ELEMS];
            #pragma unroll
            for (int j = 0; j < ELEMS; ++j)
                noise_central(b[j], mhi9, xx[j], z[j], p[j]);
            // warp-uniform rare guard: no divergence on the common path
            float zm = fmaxf(fmaxf(fmaxf(z[0], z[1]), fmaxf(z[2], z[3])),
                             fmaxf(z[4], z[5]));
            if (__builtin_expect(__any_sync(wmask, zm >= 2.5f), 0)) {
                #pragma unroll
                for (int j = 0; j < ELEMS; ++j)
                    if (z[j] >= 2.5f) p[j] = tailp(z[j]);
            }
            #pragma unroll
            for (int j = 0; j < ELEMS; ++j)
                v[j] = fma_sat(p[j], xx[j], v[j]);   // clip(v + noise)
        }
        {   // reverse diffusion: single denoise step (subtract)
            uint4 ka = sA[N_STEPS];
            uint4 kb = sB[N_STEPS];
            #pragma unroll
            for (int j = 0; j < ELEMS; ++j) {
                uint32_t b = tf_xor(ka, kb, cc[j], one);
                float xx, z, p;
                noise_central(b, mhi9, xx, z, p);
                if (z >= 2.5f) p = tailp(z);
                v[j] = fma_sat(-p, xx, v[j]);
            }
        }
        {
            float2* op = reinterpret_cast<float2*>(out + base);
            op[0] = make_float2(v[0], v[1]);
            op[1] = make_float2(v[2], v[3]);
            op[2] = make_float2(v[4], v[5]);
        }
    } else {
        // scalar tail path (not hit when n % 6 == 0, e.g. the 25165824-element shape)
        for (unsigned e = base; e < (unsigned)n; ++e) {
            float vv = x[e];
            for (int t = 0; t < N_STEPS; ++t) {
                float xx, z, p;
                noise_central(tf_xor(sA[t], sB[t], e, one), mhi9, xx, z, p);
                if (z >= 2.5f) p = tailp(z);
                vv = fma_sat(p, xx, vv);
            }
            float xx, z, p;
            noise_central(tf_xor(sA[N_STEPS], sB[N_STEPS], e, one), mhi9, xx, z, p);
            if (z >= 2.5f) p = tailp(z);
            out[e] = fma_sat(-p, xx, vv);
        }
    }
}

extern "C" void kernel_launch(void* const* d_in, const int* in_sizes, int n_in,
                              void* d_out, int out_size) {
    const float* x = (const float*)d_in[0];
    float* out     = (float*)d_out;
    int n = out_size;

    prep_keys_kernel<<<1, 1024>>>();

    unsigned threads = (unsigned)((n + ELEMS - 1) / ELEMS);
    unsigned blocks  = (threads + 255u) / 256u;
    // mhi9 = 1<<23 (for IMAD.HI) and one = 1 (for IMAD adds) kept opaque to ptxas
    diffusion_kernel<<<blocks, 256>>>(x, out, n, 1u << 23, 1u);
}

// round 13
// speedup vs baseline: 1.0488x; 1.0091x over previous
#include <cuda_runtime.h>
#include <cstdint>

#define N_STEPS 1000
#define ELEMS 6

// Per-step key schedule, 2 uint4 records:
//  A = {k0, k1, k2, k2+1},  B = {k0+2, k1+3, k2+4, k0+5}
__device__ uint4 g_keysA[N_STEPS + 1];
__device__ uint4 g_keysB[N_STEPS + 1];
// central erfinv poly coefficients re-based to s = log2(t), computed in double
__device__ float g_coef[6];

// pre-scale tail erfinv coefficients by 0.1 * sqrt(2)
#define SC(c) (0.14142136f * (c))
// tail threshold in s: z >= 2.5  <=>  s <= -5/ln2
#define S_TAIL (-7.2134752f)

// guaranteed single-instruction FFMA with [0,1] saturation (the clip)
__device__ __forceinline__ float fma_sat(float a, float b, float c) {
    float d;
    asm("fma.rn.sat.f32 %0, %1, %2, %3;" : "=f"(d) : "f"(a), "f"(b), "f"(c));
    return d;
}

// forced IMAD add (fma pipe): d = a*one + b, `one` is an opaque runtime 1
__device__ __forceinline__ uint32_t addm(uint32_t a, uint32_t b, uint32_t one) {
    uint32_t d;
    asm("mad.lo.u32 %0, %1, %2, %3;" : "=r"(d) : "r"(a), "r"(one), "r"(b));
    return d;
}

// ---------------- Threefry-2x32 ----------------
// round with the add forced onto the IMAD pipe; SHF+LOP3 stay on alu
__device__ __forceinline__ void rsm(uint32_t& x0, uint32_t& x1, int r, uint32_t one) {
    x0 = addm(x1, x0, one);                   // IMAD
    x1 = __funnelshift_l(x1, x1, r) ^ x0;     // SHF + LOP3 (alu)
}

// full 20-round block (c0 = 0 folded), returns o0 ^ o1 (partitionable random_bits)
// R10 form: separate key injections on the IMAD pipe (R11 IADD3 merge regressed).
__device__ __forceinline__ uint32_t tf_xor(uint4 ka, uint4 kb, uint32_t c1, uint32_t one) {
    uint32_t x1 = c1 + ka.y;                  // alu add
    uint32_t x0 = addm(x1, ka.x, one);        // round-1 add, x0-init folded (IMAD)
    x1 = __funnelshift_l(x1, x1, 13) ^ x0;
    rsm(x0, x1, 15, one); rsm(x0, x1, 26, one); rsm(x0, x1, 6, one);
    x0 = addm(x0, ka.y, one); x1 += ka.w;     // += k1 (IMAD) | += k2+1
    rsm(x0, x1, 17, one); rsm(x0, x1, 29, one); rsm(x0, x1, 16, one); rsm(x0, x1, 24, one);
    x0 = addm(x0, ka.z, one); x1 += kb.x;     // += k2 | += k0+2
    rsm(x0, x1, 13, one); rsm(x0, x1, 15, one); rsm(x0, x1, 26, one); rsm(x0, x1, 6, one);
    x0 = addm(x0, ka.x, one); x1 += kb.y;     // += k0 | += k1+3
    rsm(x0, x1, 17, one); rsm(x0, x1, 29, one); rsm(x0, x1, 16, one); rsm(x0, x1, 24, one);
    x0 = addm(x0, ka.y, one); x1 += kb.z;     // += k1 | += k2+4
    rsm(x0, x1, 13, one); rsm(x0, x1, 15, one); rsm(x0, x1, 26, one); rsm(x0, x1, 6, one);
    return addm(x0, ka.z, one) ^ addm(x1, kb.w, one);   // (x0+k2) ^ (x1+k0+5)
}

// plain scalar threefry for key prep (perf-irrelevant)
__device__ __forceinline__ void rs_s(uint32_t& x0, uint32_t& x1, int r) {
    x0 += x1; x1 = __funnelshift_l(x1, x1, r) ^ x0;
}
__device__ void threefry2x32_full(uint32_t k0, uint32_t k1, uint32_t c0, uint32_t c1,
                                  uint32_t& o0, uint32_t& o1) {
    const uint32_t k2 = k0 ^ k1 ^ 0x1BD11BDAu;
    uint32_t x0 = c0 + k0, x1 = c1 + k1;
    rs_s(x0,x1,13); rs_s(x0,x1,15); rs_s(x0,x1,26); rs_s(x0,x1,6);
    x0 += k1; x1 += k2 + 1u;
    rs_s(x0,x1,17); rs_s(x0,x1,29); rs_s(x0,x1,16); rs_s(x0,x1,24);
    x0 += k2; x1 += k0 + 2u;
    rs_s(x0,x1,13); rs_s(x0,x1,15); rs_s(x0,x1,26); rs_s(x0,x1,6);
    x0 += k0; x1 += k1 + 3u;
    rs_s(x0,x1,17); rs_s(x0,x1,29); rs_s(x0,x1,16); rs_s(x0,x1,24);
    x0 += k1; x1 += k2 + 4u;
    rs_s(x0,x1,13); rs_s(x0,x1,15); rs_s(x0,x1,26); rs_s(x0,x1,6);
    o0 = x0 + k2; o1 = x1 + k0 + 5u;
}

__global__ void prep_keys_kernel() {
    int t = threadIdx.x;
    // thread 0: re-base central Giles coefficients from z to s = log2(t), in double.
    //   z = a*s + b, a = -ln2, b = -2.5;  c_i = scale * a^i * sum_m k_m*C(m,i)*b^(m-i)
    if (t == 0) {
        const double kk[6] = {1.50140941, 0.246640727, -0.00417768164,
                              -0.00125372503, 0.00021858087, -4.39150654e-06};
        const double a = -0.69314718055994530942;
        const double b = -2.5;
        const int binom[6][6] = {{1,0,0,0,0,0},{1,1,0,0,0,0},{1,2,1,0,0,0},
                                 {1,3,3,1,0,0},{1,4,6,4,1,0},{1,5,10,10,5,1}};
        double ai = 1.0;
        for (int i = 0; i < 6; ++i) {
            double sum = 0.0, bp = 1.0;
            for (int m = i; m < 6; ++m) {
                sum += kk[m] * (double)binom[m][i] * bp;
                bp *= b;
            }
            g_coef[i] = (float)(0.14142136 * ai * sum);
            ai *= a;
        }
    }
    if (t > N_STEPS) return;
    uint32_t kk1 = (t < N_STEPS) ? 1u : 2u;
    uint32_t cc1 = (t < N_STEPS) ? (uint32_t)t : 999u;
    uint32_t o0, o1;
    threefry2x32_full(0u, kk1, 0u, cc1, o0, o1);
    uint32_t k0 = o0, k1 = o1, k2 = o0 ^ o1 ^ 0x1BD11BDAu;
    g_keysA[t] = make_uint4(k0, k1, k2, k2 + 1u);
    g_keysB[t] = make_uint4(k0 + 2u, k1 + 3u, k2 + 4u, k0 + 5u);
}

// rare tail branch of erfinv (w >= 5), takes s = log2(t); w = -ln2 * s
__device__ __noinline__ float tailp(float s) {
    float w = s * -0.69314718f;
    float zz = __fsqrt_rn(w) - 3.0f;
    float p = SC(-0.000200214257f);
    p = fmaf(p, zz, SC(0.000100950558f));
    p = fmaf(p, zz, SC(0.00134934322f));
    p = fmaf(p, zz, SC(-0.00367342844f));
    p = fmaf(p, zz, SC(0.00573950773f));
    p = fmaf(p, zz, SC(-0.0076224613f));
    p = fmaf(p, zz, SC(0.00943887047f));
    p = fmaf(p, zz, SC(1.00167406f));
    p = fmaf(p, zz, SC(2.83297682f));
    return p;
}

// central pipeline: bits -> {xx, s, p_central}; poly runs directly in s (no z-FMA)
__device__ __forceinline__ void noise_central(uint32_t b, uint32_t mhi9,
                                              float C0, float C1, float C2,
                                              float C3, float C4, float C5,
                                              float& xx, float& s, float& p) {
    uint32_t fbits;   // (b >> 9) | 0x3f800000  ==  hi(b * 2^23) + 0x3f800000, one IMAD.HI
    asm("mad.hi.u32 %0, %1, %2, %3;"
        : "=r"(fbits) : "r"(b), "r"(mhi9), "r"(0x3f800000u));
    float f = __uint_as_float(fbits);                // [1, 2)
    float u = f - 1.0f;                              // [0, 1), exact
    // two-op form REQUIRED: -2.99999994f is not representable (rounds to -3.0f),
    // which would make xx hit exactly -1.0 for bits < 512 -> log(0) -> NaN.
    xx = fmaf(u, 2.0f, -0.99999994f);                // uniform in [nextafter(-1,0), 1)
    float t = fmaf(xx, -xx, 1.0f);                   // 1 - x^2 > 0
    s = __log2f(t);                                  // poly is re-based in s
    p = fmaf(C5, s, C4);
    p = fmaf(p, s, C3);
    p = fmaf(p, s, C2);
    p = fmaf(p, s, C1);
    p = fmaf(p, s, C0);
}

// 768 threads/SM (3 blocks) -> 85-reg budget: room for 6 fully-parallel chains
__global__ void __launch_bounds__(256, 3)
diffusion_kernel(const float* __restrict__ x, float* __restrict__ out, int n,
                 uint32_t mhi9, uint32_t one) {
    __shared__ uint4 sA[N_STEPS + 1];
    __shared__ uint4 sB[N_STEPS + 1];
    for (int i = threadIdx.x; i <= N_STEPS; i += 256) {
        sA[i] = g_keysA[i];
        sB[i] = g_keysB[i];
    }
    __syncthreads();

    // re-based poly coefficients -> registers (uniform broadcast loads, once)
    const float C0 = g_coef[0], C1 = g_coef[1], C2 = g_coef[2];
    const float C3 = g_coef[3], C4 = g_coef[4], C5 = g_coef[5];

    unsigned tid  = blockIdx.x * 256u + threadIdx.x;
    unsigned base = tid * (unsigned)ELEMS;
    if (base >= (unsigned)n) return;

    if (base + (unsigned)ELEMS <= (unsigned)n) {
        // ---- main path: 6 independent scalar chains per thread (ILP-6) ----
        float v[ELEMS];
        {   // 6 floats = 3x float2 (8-byte aligned)
            const float2* xp = reinterpret_cast<const float2*>(x + base);
            float2 a = xp[0], b = xp[1], c = xp[2];
            v[0] = a.x; v[1] = a.y; v[2] = b.x; v[3] = b.y; v[4] = c.x; v[5] = c.y;
        }
        uint32_t cc[ELEMS];
        #pragma unroll
        for (int j = 0; j < ELEMS; ++j) cc[j] = base + (uint32_t)j;
        const unsigned wmask = __activemask();

        #pragma unroll 2
        for (int t = 0; t < N_STEPS; ++t) {
            uint4 ka = sA[t];
            uint4 kb = sB[t];
            uint32_t b[ELEMS];
            #pragma unroll
            for (int j = 0; j < ELEMS; ++j)
                b[j] = tf_xor(ka, kb, cc[j], one);
            float xx[ELEMS], s[ELEMS], p[ELEMS];
            #pragma unroll
            for (int j = 0; j < ELEMS; ++j)
                noise_central(b[j], mhi9, C0, C1, C2, C3, C4, C5, xx[j], s[j], p[j]);
            // warp-uniform rare guard: no divergence on the common path
            float sm = fminf(fminf(fminf(s[0], s[1]), fminf(s[2], s[3])),
                             fminf(s[4], s[5]));
            if (__builtin_expect(__any_sync(wmask, sm <= S_TAIL), 0)) {
                #pragma unroll
                for (int j = 0; j < ELEMS; ++j)
                    if (s[j] <= S_TAIL) p[j] = tailp(s[j]);
            }
            #pragma unroll
            for (int j = 0; j < ELEMS; ++j)
                v[j] = fma_sat(p[j], xx[j], v[j]);   // clip(v + noise)
        }
        {   // reverse diffusion: single denoise step (subtract)
            uint4 ka = sA[N_STEPS];
            uint4 kb = sB[N_STEPS];
            #pragma unroll
            for (int j = 0; j < ELEMS; ++j) {
                uint32_t b = tf_xor(ka, kb, cc[j], one);
                float xx, s, p;
                noise_central(b, mhi9, C0, C1, C2, C3, C4, C5, xx, s, p);
                if (s <= S_TAIL) p = tailp(s);
                v[j] = fma_sat(-p, xx, v[j]);
            }
        }
        {
            float2* op = reinterpret_cast<float2*>(out + base);
            op[0] = make_float2(v[0], v[1]);
            op[1] = make_float2(v[2], v[3]);
            op[2] = make_float2(v[4], v[5]);
        }
    } else {
        // scalar tail path (not hit when n % 6 == 0, e.g. the 25165824-element shape)
        for (unsigned e = base; e < (unsigned)n; ++e) {
            float vv = x[e];
            for (int t = 0; t < N_STEPS; ++t) {
                float xx, s, p;
                noise_central(tf_xor(sA[t], sB[t], e, one), mhi9,
                              C0, C1, C2, C3, C4, C5, xx, s, p);
                if (s <= S_TAIL) p = tailp(s);
                vv = fma_sat(p, xx, vv);
            }
            float xx, s, p;
            noise_central(tf_xor(sA[N_STEPS], sB[N_STEPS], e, one), mhi9,
                          C0, C1, C2, C3, C4, C5, xx, s, p);
            if (s <= S_TAIL) p = tailp(s);
            out[e] = fma_sat(-p, xx, vv);
        }
    }
}

extern "C" void kernel_launch(void* const* d_in, const int* in_sizes, int n_in,
                              void* d_out, int out_size) {
    const float* x = (const float*)d_in[0];
    float* out     = (float*)d_out;
    int n = out_size;

    prep_keys_kernel<<<1, 1024>>>();

    unsigned threads = (unsigned)((n + ELEMS - 1) / ELEMS);
    unsigned blocks  = (threads + 255u) / 256u;
    // mhi9 = 1<<23 (for IMAD.HI) and one = 1 (for IMAD adds) kept opaque to ptxas
    diffusion_kernel<<<blocks, 256>>>(x, out, n, 1u << 23, 1u);
}

// round 14
// speedup vs baseline: 1.0644x; 1.0149x over previous
#include <cuda_runtime.h>
#include <cstdint>

#define N_STEPS 1000
#define ELEMS 6

// Per-step key schedule, 2 uint4 records:
//  A = {k0, k1, k2, k2+1},  B = {k0+2, k1+3, k2+4, k0+5}
__device__ uint4 g_keysA[N_STEPS + 1];
__device__ uint4 g_keysB[N_STEPS + 1];
// central erfinv poly: rebased to s = log2(t), Chebyshev-economized to degree 4,
// computed on-device in double (5 coefficients, low -> high)
__device__ float g_coef[5];

// pre-scale tail erfinv coefficients by 0.1 * sqrt(2)
#define SC(c) (0.14142136f * (c))
// tail threshold in s: z >= 2.5  <=>  s <= -5/ln2
#define S_TAIL (-7.2134752f)

// guaranteed single-instruction FFMA with [0,1] saturation (the clip)
__device__ __forceinline__ float fma_sat(float a, float b, float c) {
    float d;
    asm("fma.rn.sat.f32 %0, %1, %2, %3;" : "=f"(d) : "f"(a), "f"(b), "f"(c));
    return d;
}

// forced IMAD add (fma pipe): d = a*one + b, `one` is an opaque runtime 1
__device__ __forceinline__ uint32_t addm(uint32_t a, uint32_t b, uint32_t one) {
    uint32_t d;
    asm("mad.lo.u32 %0, %1, %2, %3;" : "=r"(d) : "r"(a), "r"(one), "r"(b));
    return d;
}

// ---------------- Threefry-2x32 ----------------
// round with the add forced onto the IMAD pipe; SHF+LOP3 stay on alu
__device__ __forceinline__ void rsm(uint32_t& x0, uint32_t& x1, int r, uint32_t one) {
    x0 = addm(x1, x0, one);                   // IMAD
    x1 = __funnelshift_l(x1, x1, r) ^ x0;     // SHF + LOP3 (alu)
}

// full 20-round block (c0 = 0 folded), returns o0 ^ o1 (partitionable random_bits)
// R10 form: separate key injections on the IMAD pipe (R11 IADD3 merge regressed).
__device__ __forceinline__ uint32_t tf_xor(uint4 ka, uint4 kb, uint32_t c1, uint32_t one) {
    uint32_t x1 = c1 + ka.y;                  // alu add
    uint32_t x0 = addm(x1, ka.x, one);        // round-1 add, x0-init folded (IMAD)
    x1 = __funnelshift_l(x1, x1, 13) ^ x0;
    rsm(x0, x1, 15, one); rsm(x0, x1, 26, one); rsm(x0, x1, 6, one);
    x0 = addm(x0, ka.y, one); x1 += ka.w;     // += k1 (IMAD) | += k2+1
    rsm(x0, x1, 17, one); rsm(x0, x1, 29, one); rsm(x0, x1, 16, one); rsm(x0, x1, 24, one);
    x0 = addm(x0, ka.z, one); x1 += kb.x;     // += k2 | += k0+2
    rsm(x0, x1, 13, one); rsm(x0, x1, 15, one); rsm(x0, x1, 26, one); rsm(x0, x1, 6, one);
    x0 = addm(x0, ka.x, one); x1 += kb.y;     // += k0 | += k1+3
    rsm(x0, x1, 17, one); rsm(x0, x1, 29, one); rsm(x0, x1, 16, one); rsm(x0, x1, 24, one);
    x0 = addm(x0, ka.y, one); x1 += kb.z;     // += k1 | += k2+4
    rsm(x0, x1, 13, one); rsm(x0, x1, 15, one); rsm(x0, x1, 26, one); rsm(x0, x1, 6, one);
    return addm(x0, ka.z, one) ^ addm(x1, kb.w, one);   // (x0+k2) ^ (x1+k0+5)
}

// plain scalar threefry for key prep (perf-irrelevant)
__device__ __forceinline__ void rs_s(uint32_t& x0, uint32_t& x1, int r) {
    x0 += x1; x1 = __funnelshift_l(x1, x1, r) ^ x0;
}
__device__ void threefry2x32_full(uint32_t k0, uint32_t k1, uint32_t c0, uint32_t c1,
                                  uint32_t& o0, uint32_t& o1) {
    const uint32_t k2 = k0 ^ k1 ^ 0x1BD11BDAu;
    uint32_t x0 = c0 + k0, x1 = c1 + k1;
    rs_s(x0,x1,13); rs_s(x0,x1,15); rs_s(x0,x1,26); rs_s(x0,x1,6);
    x0 += k1; x1 += k2 + 1u;
    rs_s(x0,x1,17); rs_s(x0,x1,29); rs_s(x0,x1,16); rs_s(x0,x1,24);
    x0 += k2; x1 += k0 + 2u;
    rs_s(x0,x1,13); rs_s(x0,x1,15); rs_s(x0,x1,26); rs_s(x0,x1,6);
    x0 += k0; x1 += k1 + 3u;
    rs_s(x0,x1,17); rs_s(x0,x1,29); rs_s(x0,x1,16); rs_s(x0,x1,24);
    x0 += k1; x1 += k2 + 4u;
    rs_s(x0,x1,13); rs_s(x0,x1,15); rs_s(x0,x1,26); rs_s(x0,x1,6);
    o0 = x0 + k2; o1 = x1 + k0 + 5u;
}

__global__ void prep_keys_kernel() {
    int t = threadIdx.x;
    // thread 0 (double precision):
    //  1) rebase central Giles coefficients from z to s = log2(t):  z = a*s + b
    //  2) Chebyshev-economize degree 5 -> 4 on s in [A, 0], A = -5/ln2:
    //     p4 = p5 - c5 * M5,  M5 = monic degree-5 Chebyshev on [A, 0],
    //     added error <= |c5| * h^5 / 16  (~3.8e-6, 100x below existing budget)
    if (t == 0) {
        const double kk[6] = {1.50140941, 0.246640727, -0.00417768164,
                              -0.00125372503, 0.00021858087, -4.39150654e-06};
        const double a = -0.69314718055994530942;
        const double b = -2.5;
        const int binom[6][6] = {{1,0,0,0,0,0},{1,1,0,0,0,0},{1,2,1,0,0,0},
                                 {1,3,3,1,0,0},{1,4,6,4,1,0},{1,5,10,10,5,1}};
        // rebase z-poly -> s-poly cs[0..5]
        double cs[6];
        double ai = 1.0;
        for (int i = 0; i < 6; ++i) {
            double sum = 0.0, bp = 1.0;
            for (int m = i; m < 6; ++m) {
                sum += kk[m] * (double)binom[m][i] * bp;
                bp *= b;
            }
            cs[i] = 0.14142136 * ai * sum;
            ai *= a;
        }
        // monic Chebyshev M5 on [A, 0]:  M5(s) = (h^5/16) * T5((s - m)/h)
        const double A = 5.0 / a;                // -5/ln2
        const double mc = 0.5 * A;               // midpoint
        const double h  = -0.5 * A;              // half-width
        const double t5[6] = {0.0, 5.0, 0.0, -20.0, 0.0, 16.0};
        double hp[6], mp[6];                     // h^k, (-mc)^j
        hp[0] = 1.0; mp[0] = 1.0;
        for (int k = 1; k < 6; ++k) { hp[k] = hp[k-1] * h; mp[k] = mp[k-1] * (-mc); }
        double m5[6];
        for (int i = 0; i < 6; ++i) {
            double sum = 0.0;
            for (int k = i; k < 6; ++k)
                sum += t5[k] * (double)binom[k][i] * mp[k-i] / hp[k];
            m5[i] = sum * hp[5] / 16.0;
        }
        for (int i = 0; i < 5; ++i)
            g_coef[i] = (float)(cs[i] - cs[5] * m5[i]);
    }
    if (t > N_STEPS) return;
    uint32_t kk1 = (t < N_STEPS) ? 1u : 2u;
    uint32_t cc1 = (t < N_STEPS) ? (uint32_t)t : 999u;
    uint32_t o0, o1;
    threefry2x32_full(0u, kk1, 0u, cc1, o0, o1);
    uint32_t k0 = o0, k1 = o1, k2 = o0 ^ o1 ^ 0x1BD11BDAu;
    g_keysA[t] = make_uint4(k0, k1, k2, k2 + 1u);
    g_keysB[t] = make_uint4(k0 + 2u, k1 + 3u, k2 + 4u, k0 + 5u);
}

// rare tail branch of erfinv (w >= 5), takes s = log2(t); w = -ln2 * s
__device__ __noinline__ float tailp(float s) {
    float w = s * -0.69314718f;
    float zz = __fsqrt_rn(w) - 3.0f;
    float p = SC(-0.000200214257f);
    p = fmaf(p, zz, SC(0.000100950558f));
    p = fmaf(p, zz, SC(0.00134934322f));
    p = fmaf(p, zz, SC(-0.00367342844f));
    p = fmaf(p, zz, SC(0.00573950773f));
    p = fmaf(p, zz, SC(-0.0076224613f));
    p = fmaf(p, zz, SC(0.00943887047f));
    p = fmaf(p, zz, SC(1.00167406f));
    p = fmaf(p, zz, SC(2.83297682f));
    return p;
}

// central pipeline: bits -> {xx, s, p_central}; degree-4 economized poly in s
__device__ __forceinline__ void noise_central(uint32_t b, uint32_t mhi9,
                                              float C0, float C1, float C2,
                                              float C3, float C4,
                                              float& xx, float& s, float& p) {
    uint32_t fbits;   // (b >> 9) | 0x3f800000  ==  hi(b * 2^23) + 0x3f800000, one IMAD.HI
    asm("mad.hi.u32 %0, %1, %2, %3;"
        : "=r"(fbits) : "r"(b), "r"(mhi9), "r"(0x3f800000u));
    float f = __uint_as_float(fbits);                // [1, 2)
    float u = f - 1.0f;                              // [0, 1), exact
    // two-op form REQUIRED: -2.99999994f is not representable (rounds to -3.0f),
    // which would make xx hit exactly -1.0 for bits < 512 -> log(0) -> NaN.
    xx = fmaf(u, 2.0f, -0.99999994f);                // uniform in [nextafter(-1,0), 1)
    float t = fmaf(xx, -xx, 1.0f);                   // 1 - x^2 > 0
    s = __log2f(t);                                  // poly evaluated directly in s
    p = fmaf(C4, s, C3);
    p = fmaf(p, s, C2);
    p = fmaf(p, s, C1);
    p = fmaf(p, s, C0);
}

// 768 threads/SM (3 blocks) -> 85-reg budget: room for 6 fully-parallel chains
__global__ void __launch_bounds__(256, 3)
diffusion_kernel(const float* __restrict__ x, float* __restrict__ out, int n,
                 uint32_t mhi9, uint32_t one) {
    __shared__ uint4 sA[N_STEPS + 1];
    __shared__ uint4 sB[N_STEPS + 1];
    for (int i = threadIdx.x; i <= N_STEPS; i += 256) {
        sA[i] = g_keysA[i];
        sB[i] = g_keysB[i];
    }
    __syncthreads();

    // economized poly coefficients -> registers (uniform broadcast loads, once)
    const float C0 = g_coef[0], C1 = g_coef[1], C2 = g_coef[2];
    const float C3 = g_coef[3], C4 = g_coef[4];

    unsigned tid  = blockIdx.x * 256u + threadIdx.x;
    unsigned base = tid * (unsigned)ELEMS;
    if (base >= (unsigned)n) return;

    if (base + (unsigned)ELEMS <= (unsigned)n) {
        // ---- main path: 6 independent scalar chains per thread (ILP-6) ----
        float v[ELEMS];
        {   // 6 floats = 3x float2 (8-byte aligned)
            const float2* xp = reinterpret_cast<const float2*>(x + base);
            float2 a = xp[0], b = xp[1], c = xp[2];
            v[0] = a.x; v[1] = a.y; v[2] = b.x; v[3] = b.y; v[4] = c.x; v[5] = c.y;
        }
        uint32_t cc[ELEMS];
        #pragma unroll
        for (int j = 0; j < ELEMS; ++j) cc[j] = base + (uint32_t)j;
        const unsigned wmask = __activemask();

        #pragma unroll 2
        for (int t = 0; t < N_STEPS; ++t) {
            uint4 ka = sA[t];
            uint4 kb = sB[t];
            uint32_t b[ELEMS];
            #pragma unroll
            for (int j = 0; j < ELEMS; ++j)
                b[j] = tf_xor(ka, kb, cc[j], one);
            float xx[ELEMS], s[ELEMS], p[ELEMS];
            #pragma unroll
            for (int j = 0; j < ELEMS; ++j)
                noise_central(b[j], mhi9, C0, C1, C2, C3, C4, xx[j], s[j], p[j]);
            // warp-uniform rare guard: no divergence on the common path
            float sm = fminf(fminf(fminf(s[0], s[1]), fminf(s[2], s[3])),
                             fminf(s[4], s[5]));
            if (__builtin_expect(__any_sync(wmask, sm <= S_TAIL), 0)) {
                #pragma unroll
                for (int j = 0; j < ELEMS; ++j)
                    if (s[j] <= S_TAIL) p[j] = tailp(s[j]);
            }
            #pragma unroll
            for (int j = 0; j < ELEMS; ++j)
                v[j] = fma_sat(p[j], xx[j], v[j]);   // clip(v + noise)
        }
        {   // reverse diffusion: single denoise step (subtract)
            uint4 ka = sA[N_STEPS];
            uint4 kb = sB[N_STEPS];
            #pragma unroll
            for (int j = 0; j < ELEMS; ++j) {
                uint32_t b = tf_xor(ka, kb, cc[j], one);
                float xx, s, p;
                noise_central(b, mhi9, C0, C1, C2, C3, C4, xx, s, p);
                if (s <= S_TAIL) p = tailp(s);
                v[j] = fma_sat(-p, xx, v[j]);
            }
        }
        {
            float2* op = reinterpret_cast<float2*>(out + base);
            op[0] = make_float2(v[0], v[1]);
            op[1] = make_float2(v[2], v[3]);
            op[2] = make_float2(v[4], v[5]);
        }
    } else {
        // scalar tail path (not hit when n % 6 == 0, e.g. the 25165824-element shape)
        for (unsigned e = base; e < (unsigned)n; ++e) {
            float vv = x[e];
            for (int t = 0; t < N_STEPS; ++t) {
                float xx, s, p;
                noise_central(tf_xor(sA[t], sB[t], e, one), mhi9,
                              C0, C1, C2, C3, C4, xx, s, p);
                if (s <= S_TAIL) p = tailp(s);
                vv = fma_sat(p, xx, vv);
            }
            float xx, s, p;
            noise_central(tf_xor(sA[N_STEPS], sB[N_STEPS], e, one), mhi9,
                          C0, C1, C2, C3, C4, xx, s, p);
            if (s <= S_TAIL) p = tailp(s);
            out[e] = fma_sat(-p, xx, vv);
        }
    }
}

extern "C" void kernel_launch(void* const* d_in, const int* in_sizes, int n_in,
                              void* d_out, int out_size) {
    const float* x = (const float*)d_in[0];
    float* out     = (float*)d_out;
    int n = out_size;

    prep_keys_kernel<<<1, 1024>>>();

    unsigned threads = (unsigned)((n + ELEMS - 1) / ELEMS);
    unsigned blocks  = (threads + 255u) / 256u;
    // mhi9 = 1<<23 (for IMAD.HI) and one = 1 (for IMAD adds) kept opaque to ptxas
    diffusion_kernel<<<blocks, 256>>>(x, out, n, 1u << 23, 1u);
}